// round 14
// baseline (speedup 1.0000x reference)
#include <cuda_runtime.h>
#include <cstdint>

#define H 480
#define W 640
#define P 256

// swizzled, guard-padded row layout (shared by g_box and the smem band)
#define SWQ 176                   // 16B quads per row (22 x 8-quad blocks)
#define SWF (SWQ * 4)             // 704 floats per row
#define GQ  4                     // left guard quads (16 floats)

// descriptor tiling
#define TY 8                      // output rows per block
#define BAND (TY + 32)            // 40 band rows
#define NTHREADS 160              // 2 slabs x 80 col-threads
#define GPAIRS 8                  // pairs per block
#define SMEM_DATA_BYTES (BAND * SWF * 4)        // 112,640
#define SMEM_BYTES (SMEM_DATA_BYTES + 16)       // + mbarrier -> 2 CTAs/SM fit

// Pre-swizzled box-average image with replicate guards (allocation-free)
__device__ __align__(16) float g_box[H * SWF];

// Quad swizzle: XOR quad index with its 128B-block index (bits [3:6)).
// For stride-2-quad lane patterns this spreads 32 lanes uniformly over all
// 8 bank-groups (4 lanes each) -> conflict-free LDS.128.
__device__ __host__ __forceinline__ int swzq(int q) { return q ^ ((q >> 3) & 7); }

// ---------------------------------------------------------------------------
// Packed f32x2 helpers
// ---------------------------------------------------------------------------
__device__ __forceinline__ uint64_t pk2(float lo, float hi) {
    uint64_t r; asm("mov.b64 %0, {%1, %2};" : "=l"(r) : "f"(lo), "f"(hi)); return r;
}
__device__ __forceinline__ uint64_t mul2(uint64_t a, uint64_t b) {
    uint64_t r; asm("mul.rn.f32x2 %0, %1, %2;" : "=l"(r) : "l"(a), "l"(b)); return r;
}
__device__ __forceinline__ uint64_t fma2(uint64_t a, uint64_t b, uint64_t c) {
    uint64_t r; asm("fma.rn.f32x2 %0, %1, %2, %3;" : "=l"(r) : "l"(a), "l"(b), "l"(c)); return r;
}
__device__ __forceinline__ uint64_t add2(uint64_t a, uint64_t b) {
    uint64_t r; asm("add.rn.f32x2 %0, %1, %2;" : "=l"(r) : "l"(a), "l"(b)); return r;
}
__device__ __forceinline__ float2 upk2(uint64_t a) {
    float2 f; asm("mov.b64 {%0, %1}, %2;" : "=f"(f.x), "=f"(f.y) : "l"(a)); return f;
}

// ---------------------------------------------------------------------------
// Fused 5x5 box average -> pre-swizzled guard-padded g_box.
// 168 groups per row: 160 interior float4 + 4 left-guard + 4 right-guard quads.
// ---------------------------------------------------------------------------
__global__ void box_kernel(const float* __restrict__ x) {
    int idx = blockIdx.x * blockDim.x + threadIdx.x;
    if (idx >= H * 168) return;
    int y = idx / 168;
    int t = idx - y * 168;
    float* orow = g_box + y * SWF;

    if (t < 160) {
        float4 s = make_float4(0.f, 0.f, 0.f, 0.f);
        if (t >= 1 && t <= 158) {
#pragma unroll
            for (int d = -2; d <= 2; d++) {
                int yc = min(max(y + d, 0), H - 1);
                const float* row = x + yc * W;
                float4 m1 = __ldg((const float4*)(row + 4 * t - 4));
                float4 c0 = __ldg((const float4*)(row + 4 * t));
                float4 p1 = __ldg((const float4*)(row + 4 * t + 4));
                float ss = c0.x + c0.y + c0.z;
                s.x += ss + m1.z + m1.w;
                s.y += ss + m1.w + c0.w;
                s.z += ss + c0.w + p1.x;
                s.w += c0.y + c0.z + c0.w + p1.x + p1.y;
            }
        } else {
            float r[4] = {0.f, 0.f, 0.f, 0.f};
#pragma unroll
            for (int d = -2; d <= 2; d++) {
                int yc = min(max(y + d, 0), H - 1);
                const float* row = x + yc * W;
#pragma unroll
                for (int k = 0; k < 4; k++) {
                    int xx = 4 * t + k;
#pragma unroll
                    for (int e = -2; e <= 2; e++) {
                        int xc = min(max(xx + e, 0), W - 1);
                        r[k] += row[xc];
                    }
                }
            }
            s = make_float4(r[0], r[1], r[2], r[3]);
        }
        const float inv = 1.0f / 25.0f;
        s.x *= inv; s.y *= inv; s.z *= inv; s.w *= inv;
        *(float4*)(orow + swzq(GQ + t) * 4) = s;
    } else {
        // guard quads: replicate border box value
        bool left = (t < 164);
        float v = 0.f;
#pragma unroll
        for (int d = -2; d <= 2; d++) {
            int yc = min(max(y + d, 0), H - 1);
            const float* row = x + yc * W;
            if (left) v += 3.f * row[0] + row[1] + row[2];
            else      v += 3.f * row[W - 1] + row[W - 2] + row[W - 3];
        }
        v *= (1.0f / 25.0f);
        int q = left ? (t - 160) : (GQ + 160 + (t - 164));  // 0..3 or 164..167
        *(float4*)(orow + swzq(q) * 4) = make_float4(v, v, v, v);
    }
}

// ---------------------------------------------------------------------------
// Horizontal lerp of one band row: 3 swizzled LDS.128 -> 8 outputs (4 pairs)
// ---------------------------------------------------------------------------
template <int RR>
__device__ __forceinline__ void hrow8(const float* __restrict__ sp,
                                      int o0, int o1, int o2,
                                      uint64_t fx2, uint64_t omfx2, uint64_t* h) {
    float4 A = *(const float4*)(sp + o0);
    float4 B = *(const float4*)(sp + o1);
    float4 C = *(const float4*)(sp + o2);
    float w0, w1, w2, w3, w4, w5, w6, w7, w8;
    if      (RR == 0) { w0=A.x; w1=A.y; w2=A.z; w3=A.w; w4=B.x; w5=B.y; w6=B.z; w7=B.w; w8=C.x; }
    else if (RR == 1) { w0=A.y; w1=A.z; w2=A.w; w3=B.x; w4=B.y; w5=B.z; w6=B.w; w7=C.x; w8=C.y; }
    else if (RR == 2) { w0=A.z; w1=A.w; w2=B.x; w3=B.y; w4=B.z; w5=B.w; w6=C.x; w7=C.y; w8=C.z; }
    else              { w0=A.w; w1=B.x; w2=B.y; w3=B.z; w4=B.w; w5=C.x; w6=C.y; w7=C.z; w8=C.w; }
    h[0] = fma2(pk2(w1, w2), fx2, mul2(pk2(w0, w1), omfx2));
    h[1] = fma2(pk2(w3, w4), fx2, mul2(pk2(w2, w3), omfx2));
    h[2] = fma2(pk2(w5, w6), fx2, mul2(pk2(w4, w5), omfx2));
    h[3] = fma2(pk2(w7, w8), fx2, mul2(pk2(w6, w7), omfx2));
}

// ---------------------------------------------------------------------------
// 4-row chained sample, 8 cols wide. SUB folds subtraction via negated fy.
// acc: 16 packed pairs (4 rows x 4 pairs).
// ---------------------------------------------------------------------------
template <int RR, bool SUB>
__device__ __forceinline__ void rows4x8(const float* __restrict__ sp,
                                        int o0, int o1, int o2,
                                        float fx, float fy, uint64_t* acc) {
    uint64_t fx2   = pk2(fx, fx);
    uint64_t omfx2 = pk2(1.0f - fx, 1.0f - fx);
    const float sgn = SUB ? -1.0f : 1.0f;
    uint64_t fy2   = pk2(sgn * fy, sgn * fy);
    uint64_t omfy2 = pk2(sgn * (1.0f - fy), sgn * (1.0f - fy));

    uint64_t hp[4], hc[4];
    hrow8<RR>(sp, o0, o1, o2, fx2, omfx2, hp);
#pragma unroll
    for (int i = 0; i < 4; i++) {
        sp += SWF;
        hrow8<RR>(sp, o0, o1, o2, fx2, omfx2, hc);
#pragma unroll
        for (int k = 0; k < 4; k++) {
            uint64_t o = fma2(hc[k], fy2, mul2(hp[k], omfy2));
            if (SUB) acc[4 * i + k] = add2(acc[4 * i + k], o);
            else     acc[4 * i + k] = o;
            hp[k] = hc[k];
        }
    }
}

template <bool SUB>
__device__ __forceinline__ void band_sample(const float* __restrict__ sb,
                                            int y0, int ybase, int gx,
                                            float dy, float dx, uint64_t* acc) {
    float py0 = (float)ybase + dy;
    float yAf = floorf(py0);
    float fy  = py0 - yAf;
    int slot0 = (int)yAf - (y0 - 16);     // in [0, BAND-5]

    float ixf = floorf(dx);
    float fx  = dx - ixf;
    int c  = gx + (int)ixf;               // in [-16, 647]
    int qb = (c >> 2) + GQ;               // quad index incl guard, [0, 165]
    int rr = c & 3;                       // block-uniform
    int o0 = swzq(qb) * 4, o1 = swzq(qb + 1) * 4, o2 = swzq(qb + 2) * 4;

    const float* sp = sb + slot0 * SWF;
    switch (rr) {                         // uniform branch
        case 0:  rows4x8<0, SUB>(sp, o0, o1, o2, fx, fy, acc); break;
        case 1:  rows4x8<1, SUB>(sp, o0, o1, o2, fx, fy, acc); break;
        case 2:  rows4x8<2, SUB>(sp, o0, o1, o2, fx, fy, acc); break;
        default: rows4x8<3, SUB>(sp, o0, o1, o2, fx, fy, acc); break;
    }
}

// ---------------------------------------------------------------------------
// Descriptor kernel: TMA-bulk stages a 40-row pre-swizzled band. 112.6 KB
// smem -> 2 CTAs co-resident per SM, so one block's TMA fill + mbarrier wait
// hides under the other block's compute. 160 threads = 2 slabs x 80 cols.
// ---------------------------------------------------------------------------
__global__ void __launch_bounds__(NTHREADS, 2) descriptor_kernel(
    const float* __restrict__ offs, float* __restrict__ out)
{
    extern __shared__ float sb[];
    const int y0  = blockIdx.x * TY;
    const int tid = threadIdx.x;
    uint32_t sbu  = (uint32_t)__cvta_generic_to_shared(sb);
    uint32_t mbar = sbu + SMEM_DATA_BYTES;

    if (tid == 0) {
        asm volatile("mbarrier.init.shared.b64 [%0], 1;" :: "r"(mbar) : "memory");
        asm volatile("mbarrier.arrive.expect_tx.shared.b64 _, [%0], %1;"
                     :: "r"(mbar), "r"((uint32_t)(BAND * SWF * 4)) : "memory");
    }
    __syncthreads();
    if (tid < BAND) {
        int gy = min(max(y0 - 16 + tid, 0), H - 1);
        uint32_t dst = sbu + tid * (SWF * 4);
        const float* src = g_box + gy * SWF;
        asm volatile(
            "cp.async.bulk.shared::cluster.global.mbarrier::complete_tx::bytes "
            "[%0], [%1], %2, [%3];"
            :: "r"(dst), "l"(src), "r"((uint32_t)(SWF * 4)), "r"(mbar) : "memory");
    }
    // all threads wait for band (parity 0, acquire)
    {
        uint32_t done;
        asm volatile(
            "{\n\t.reg .pred p;\n\t"
            "mbarrier.try_wait.parity.acquire.cta.shared::cta.b64 p, [%1], %2;\n\t"
            "selp.b32 %0, 1, 0, p;\n\t}"
            : "=r"(done) : "r"(mbar), "r"(0u) : "memory");
        if (!done) {
            asm volatile(
                "{\n\t.reg .pred P1;\n\t"
                "WL%=:\n\t"
                "mbarrier.try_wait.parity.acquire.cta.shared::cta.b64 P1, [%0], %1, 0x989680;\n\t"
                "@P1 bra.uni WD%=;\n\t"
                "bra.uni WL%=;\n\t"
                "WD%=:\n\t}"
                :: "r"(mbar), "r"(0u) : "memory");
        }
    }

    const int slab  = tid / 80;             // 0..1
    const int col   = tid - slab * 80;      // 0..79
    const int gx    = col * 8;
    const int ybase = y0 + slab * 4;

    const int pbase = blockIdx.y * GPAIRS;
#pragma unroll 1
    for (int g = 0; g < GPAIRS; g++) {
        int p = pbase + g;
        float4 od = __ldg((const float4*)(offs + 4 * p));  // dy1,dx1,dy2,dx2

        uint64_t acc[16];
        band_sample<false>(sb, y0, ybase, gx, od.x, od.y, acc);
        band_sample<true >(sb, y0, ybase, gx, od.z, od.w, acc);

        float* op = out + ((size_t)p * H + ybase) * W + gx;
#pragma unroll
        for (int i = 0; i < 4; i++) {
            float2 a = upk2(acc[4 * i + 0]);
            float2 b = upk2(acc[4 * i + 1]);
            float2 c = upk2(acc[4 * i + 2]);
            float2 d = upk2(acc[4 * i + 3]);
            __stcs((float4*)(op + (size_t)i * W),     make_float4(a.x, a.y, b.x, b.y));
            __stcs((float4*)(op + (size_t)i * W + 4), make_float4(c.x, c.y, d.x, d.y));
        }
    }
}

extern "C" void kernel_launch(void* const* d_in, const int* in_sizes, int n_in,
                              void* d_out, int out_size) {
    const float* x    = (const float*)d_in[0];   // [1,1,480,640]
    const float* offs = (const float*)d_in[1];   // [256,2,2]
    float* out = (float*)d_out;                  // [1,256,480,640]

    cudaFuncSetAttribute(descriptor_kernel,
                         cudaFuncAttributeMaxDynamicSharedMemorySize, SMEM_BYTES);

    const int nbox = H * 168;                    // 80640
    box_kernel<<<(nbox + 255) / 256, 256>>>(x);

    dim3 grid(H / TY, P / GPAIRS, 1);            // (60, 32) = 1920 blocks
    descriptor_kernel<<<grid, NTHREADS, SMEM_BYTES>>>(offs, out);
}

// round 15
// speedup vs baseline: 1.0787x; 1.0787x over previous
#include <cuda_runtime.h>
#include <cstdint>

#define H 480
#define W 640
#define P 256

// swizzled, guard-padded row layout (shared by g_box and the smem band)
#define SWQ 176                   // 16B quads per row
#define SWF (SWQ * 4)             // 704 floats per row
#define GQ  4                     // left guard quads (16 floats)

// descriptor tiling (R11 geometry — best measured)
#define TY 16                     // output rows per block
#define BAND (TY + 32)            // 48 band rows
#define NTHREADS 320              // 4 slabs x 80 col-threads
#define GPAIRS 8                  // pairs per block
#define SMEM_DATA_BYTES (BAND * SWF * 4)        // 135168
#define SMEM_BYTES (SMEM_DATA_BYTES + 16)       // + mbarrier

// Pre-swizzled box-average image with replicate guards (allocation-free)
__device__ __align__(16) float g_box[H * SWF];

// 16B-quad XOR swizzle (R11 original — measured conflict-free for the
// stride-2-quad access pattern; R14's 3-bit variant was a regression)
__device__ __host__ __forceinline__ int swzq(int q) { return q ^ ((q >> 3) & 1); }

// ---------------------------------------------------------------------------
// Packed f32x2 helpers
// ---------------------------------------------------------------------------
__device__ __forceinline__ uint64_t pk2(float lo, float hi) {
    uint64_t r; asm("mov.b64 %0, {%1, %2};" : "=l"(r) : "f"(lo), "f"(hi)); return r;
}
__device__ __forceinline__ uint64_t mul2(uint64_t a, uint64_t b) {
    uint64_t r; asm("mul.rn.f32x2 %0, %1, %2;" : "=l"(r) : "l"(a), "l"(b)); return r;
}
__device__ __forceinline__ uint64_t fma2(uint64_t a, uint64_t b, uint64_t c) {
    uint64_t r; asm("fma.rn.f32x2 %0, %1, %2, %3;" : "=l"(r) : "l"(a), "l"(b), "l"(c)); return r;
}
__device__ __forceinline__ uint64_t sub2(uint64_t a, uint64_t b) {
    uint64_t r; asm("sub.rn.f32x2 %0, %1, %2;" : "=l"(r) : "l"(a), "l"(b)); return r;
}
__device__ __forceinline__ float2 upk2(uint64_t a) {
    float2 f; asm("mov.b64 {%0, %1}, %2;" : "=f"(f.x), "=f"(f.y) : "l"(a)); return f;
}

// ---------------------------------------------------------------------------
// Fused 5x5 box average -> pre-swizzled guard-padded g_box.
// ---------------------------------------------------------------------------
__global__ void box_kernel(const float* __restrict__ x) {
    int idx = blockIdx.x * blockDim.x + threadIdx.x;
    if (idx >= H * 168) return;
    int y = idx / 168;
    int t = idx - y * 168;
    float* orow = g_box + y * SWF;

    if (t < 160) {
        float4 s = make_float4(0.f, 0.f, 0.f, 0.f);
        if (t >= 1 && t <= 158) {
#pragma unroll
            for (int d = -2; d <= 2; d++) {
                int yc = min(max(y + d, 0), H - 1);
                const float* row = x + yc * W;
                float4 m1 = __ldg((const float4*)(row + 4 * t - 4));
                float4 c0 = __ldg((const float4*)(row + 4 * t));
                float4 p1 = __ldg((const float4*)(row + 4 * t + 4));
                float ss = c0.x + c0.y + c0.z;
                s.x += ss + m1.z + m1.w;
                s.y += ss + m1.w + c0.w;
                s.z += ss + c0.w + p1.x;
                s.w += c0.y + c0.z + c0.w + p1.x + p1.y;
            }
        } else {
            float r[4] = {0.f, 0.f, 0.f, 0.f};
#pragma unroll
            for (int d = -2; d <= 2; d++) {
                int yc = min(max(y + d, 0), H - 1);
                const float* row = x + yc * W;
#pragma unroll
                for (int k = 0; k < 4; k++) {
                    int xx = 4 * t + k;
#pragma unroll
                    for (int e = -2; e <= 2; e++) {
                        int xc = min(max(xx + e, 0), W - 1);
                        r[k] += row[xc];
                    }
                }
            }
            s = make_float4(r[0], r[1], r[2], r[3]);
        }
        const float inv = 1.0f / 25.0f;
        s.x *= inv; s.y *= inv; s.z *= inv; s.w *= inv;
        *(float4*)(orow + swzq(GQ + t) * 4) = s;
    } else {
        bool left = (t < 164);
        float v = 0.f;
#pragma unroll
        for (int d = -2; d <= 2; d++) {
            int yc = min(max(y + d, 0), H - 1);
            const float* row = x + yc * W;
            if (left) v += 3.f * row[0] + row[1] + row[2];
            else      v += 3.f * row[W - 1] + row[W - 2] + row[W - 3];
        }
        v *= (1.0f / 25.0f);
        int q = left ? (t - 160) : (GQ + 160 + (t - 164));
        *(float4*)(orow + swzq(q) * 4) = make_float4(v, v, v, v);
    }
}

// ---------------------------------------------------------------------------
// Horizontal lerp of one band row: 3 swizzled LDS.128 -> 4 packed pairs
// ---------------------------------------------------------------------------
template <int RR>
__device__ __forceinline__ void hrow8(const float* __restrict__ sp,
                                      int o0, int o1, int o2,
                                      uint64_t fx2, uint64_t omfx2, uint64_t* h) {
    float4 A = *(const float4*)(sp + o0);
    float4 B = *(const float4*)(sp + o1);
    float4 C = *(const float4*)(sp + o2);
    float w0, w1, w2, w3, w4, w5, w6, w7, w8;
    if      (RR == 0) { w0=A.x; w1=A.y; w2=A.z; w3=A.w; w4=B.x; w5=B.y; w6=B.z; w7=B.w; w8=C.x; }
    else if (RR == 1) { w0=A.y; w1=A.z; w2=A.w; w3=B.x; w4=B.y; w5=B.z; w6=B.w; w7=C.x; w8=C.y; }
    else if (RR == 2) { w0=A.z; w1=A.w; w2=B.x; w3=B.y; w4=B.z; w5=B.w; w6=C.x; w7=C.y; w8=C.z; }
    else              { w0=A.w; w1=B.x; w2=B.y; w3=B.z; w4=B.w; w5=C.x; w6=C.y; w7=C.z; w8=C.w; }
    h[0] = fma2(pk2(w1, w2), fx2, mul2(pk2(w0, w1), omfx2));
    h[1] = fma2(pk2(w3, w4), fx2, mul2(pk2(w2, w3), omfx2));
    h[2] = fma2(pk2(w5, w6), fx2, mul2(pk2(w4, w5), omfx2));
    h[3] = fma2(pk2(w7, w8), fx2, mul2(pk2(w6, w7), omfx2));
}

// ---------------------------------------------------------------------------
// Interleaved pair loop: both samples chained per row, result stored
// immediately (no accumulator registers; 6 independent LDS per step).
// ---------------------------------------------------------------------------
struct SampP {
    const float* sp;      // band row pointer (slot0)
    int o0, o1, o2;       // swizzled quad offsets
    uint64_t fx2, omfx2;  // horizontal weights (packed)
    uint64_t fy2, omfy2;  // vertical weights (packed)
};

template <int R1, int R2>
__device__ __forceinline__ void pair_rows(SampP s1, SampP s2, float* op) {
    uint64_t hp1[4], hp2[4], hc1[4], hc2[4];
    hrow8<R1>(s1.sp, s1.o0, s1.o1, s1.o2, s1.fx2, s1.omfx2, hp1);
    hrow8<R2>(s2.sp, s2.o0, s2.o1, s2.o2, s2.fx2, s2.omfx2, hp2);
#pragma unroll
    for (int i = 0; i < 4; i++) {
        s1.sp += SWF;
        s2.sp += SWF;
        hrow8<R1>(s1.sp, s1.o0, s1.o1, s1.o2, s1.fx2, s1.omfx2, hc1);
        hrow8<R2>(s2.sp, s2.o0, s2.o1, s2.o2, s2.fx2, s2.omfx2, hc2);
        uint64_t d0 = sub2(fma2(hc1[0], s1.fy2, mul2(hp1[0], s1.omfy2)),
                           fma2(hc2[0], s2.fy2, mul2(hp2[0], s2.omfy2)));
        uint64_t d1 = sub2(fma2(hc1[1], s1.fy2, mul2(hp1[1], s1.omfy2)),
                           fma2(hc2[1], s2.fy2, mul2(hp2[1], s2.omfy2)));
        uint64_t d2 = sub2(fma2(hc1[2], s1.fy2, mul2(hp1[2], s1.omfy2)),
                           fma2(hc2[2], s2.fy2, mul2(hp2[2], s2.omfy2)));
        uint64_t d3 = sub2(fma2(hc1[3], s1.fy2, mul2(hp1[3], s1.omfy2)),
                           fma2(hc2[3], s2.fy2, mul2(hp2[3], s2.omfy2)));
        float2 a = upk2(d0), b = upk2(d1), c = upk2(d2), d = upk2(d3);
        __stcs((float4*)(op),     make_float4(a.x, a.y, b.x, b.y));
        __stcs((float4*)(op + 4), make_float4(c.x, c.y, d.x, d.y));
        op += W;
#pragma unroll
        for (int k = 0; k < 4; k++) { hp1[k] = hc1[k]; hp2[k] = hc2[k]; }
    }
}

__device__ __forceinline__ SampP make_samp(const float* __restrict__ sb,
                                           int y0, int ybase, int gx,
                                           float dy, float dx, float sgn,
                                           int& rr) {
    SampP s;
    float py0 = (float)ybase + dy;
    float yAf = floorf(py0);
    float fy  = py0 - yAf;
    int slot0 = (int)yAf - (y0 - 16);
    float ixf = floorf(dx);
    float fx  = dx - ixf;
    int c  = gx + (int)ixf;
    int qb = (c >> 2) + GQ;
    rr = c & 3;
    s.o0 = swzq(qb) * 4; s.o1 = swzq(qb + 1) * 4; s.o2 = swzq(qb + 2) * 4;
    s.sp = sb + slot0 * SWF;
    s.fx2 = pk2(fx, fx); s.omfx2 = pk2(1.0f - fx, 1.0f - fx);
    s.fy2 = pk2(fy, fy); s.omfy2 = pk2(1.0f - fy, 1.0f - fy);
    (void)sgn;
    return s;
}

// ---------------------------------------------------------------------------
// Descriptor kernel: TMA-bulk stages a 48-row pre-swizzled band, then
// 4 slabs x 80 cols compute 8 pairs with the interleaved row loop.
// ---------------------------------------------------------------------------
__global__ void __launch_bounds__(NTHREADS) descriptor_kernel(
    const float* __restrict__ offs, float* __restrict__ out)
{
    extern __shared__ float sb[];
    const int y0  = blockIdx.x * TY;
    const int tid = threadIdx.x;
    uint32_t sbu  = (uint32_t)__cvta_generic_to_shared(sb);
    uint32_t mbar = sbu + SMEM_DATA_BYTES;

    if (tid == 0) {
        asm volatile("mbarrier.init.shared.b64 [%0], 1;" :: "r"(mbar) : "memory");
        asm volatile("mbarrier.arrive.expect_tx.shared.b64 _, [%0], %1;"
                     :: "r"(mbar), "r"((uint32_t)(BAND * SWF * 4)) : "memory");
    }
    __syncthreads();
    if (tid < BAND) {
        int gy = min(max(y0 - 16 + tid, 0), H - 1);
        uint32_t dst = sbu + tid * (SWF * 4);
        const float* src = g_box + gy * SWF;
        asm volatile(
            "cp.async.bulk.shared::cluster.global.mbarrier::complete_tx::bytes "
            "[%0], [%1], %2, [%3];"
            :: "r"(dst), "l"(src), "r"((uint32_t)(SWF * 4)), "r"(mbar) : "memory");
    }
    {
        uint32_t done;
        asm volatile(
            "{\n\t.reg .pred p;\n\t"
            "mbarrier.try_wait.parity.acquire.cta.shared::cta.b64 p, [%1], %2;\n\t"
            "selp.b32 %0, 1, 0, p;\n\t}"
            : "=r"(done) : "r"(mbar), "r"(0u) : "memory");
        if (!done) {
            asm volatile(
                "{\n\t.reg .pred P1;\n\t"
                "WL%=:\n\t"
                "mbarrier.try_wait.parity.acquire.cta.shared::cta.b64 P1, [%0], %1, 0x989680;\n\t"
                "@P1 bra.uni WD%=;\n\t"
                "bra.uni WL%=;\n\t"
                "WD%=:\n\t}"
                :: "r"(mbar), "r"(0u) : "memory");
        }
    }

    const int slab  = tid / 80;             // 0..3
    const int col   = tid - slab * 80;      // 0..79
    const int gx    = col * 8;
    const int ybase = y0 + slab * 4;

    const int pbase = blockIdx.y * GPAIRS;
#pragma unroll 1
    for (int g = 0; g < GPAIRS; g++) {
        int p = pbase + g;
        float4 od = __ldg((const float4*)(offs + 4 * p));  // dy1,dx1,dy2,dx2

        int rr1, rr2;
        SampP s1 = make_samp(sb, y0, ybase, gx, od.x, od.y, 1.f, rr1);
        SampP s2 = make_samp(sb, y0, ybase, gx, od.z, od.w, 1.f, rr2);
        float* op = out + ((size_t)p * H + ybase) * W + gx;

        switch (rr1 * 4 + rr2) {             // block-uniform dispatch
            case  0: pair_rows<0,0>(s1, s2, op); break;
            case  1: pair_rows<0,1>(s1, s2, op); break;
            case  2: pair_rows<0,2>(s1, s2, op); break;
            case  3: pair_rows<0,3>(s1, s2, op); break;
            case  4: pair_rows<1,0>(s1, s2, op); break;
            case  5: pair_rows<1,1>(s1, s2, op); break;
            case  6: pair_rows<1,2>(s1, s2, op); break;
            case  7: pair_rows<1,3>(s1, s2, op); break;
            case  8: pair_rows<2,0>(s1, s2, op); break;
            case  9: pair_rows<2,1>(s1, s2, op); break;
            case 10: pair_rows<2,2>(s1, s2, op); break;
            case 11: pair_rows<2,3>(s1, s2, op); break;
            case 12: pair_rows<3,0>(s1, s2, op); break;
            case 13: pair_rows<3,1>(s1, s2, op); break;
            case 14: pair_rows<3,2>(s1, s2, op); break;
            default: pair_rows<3,3>(s1, s2, op); break;
        }
    }
}

extern "C" void kernel_launch(void* const* d_in, const int* in_sizes, int n_in,
                              void* d_out, int out_size) {
    const float* x    = (const float*)d_in[0];   // [1,1,480,640]
    const float* offs = (const float*)d_in[1];   // [256,2,2]
    float* out = (float*)d_out;                  // [1,256,480,640]

    cudaFuncSetAttribute(descriptor_kernel,
                         cudaFuncAttributeMaxDynamicSharedMemorySize, SMEM_BYTES);

    const int nbox = H * 168;                    // 80640
    box_kernel<<<(nbox + 255) / 256, 256>>>(x);

    dim3 grid(H / TY, P / GPAIRS, 1);            // (30, 32) = 960 blocks
    descriptor_kernel<<<grid, NTHREADS, SMEM_BYTES>>>(offs, out);
}

// round 16
// speedup vs baseline: 1.1289x; 1.0465x over previous
#include <cuda_runtime.h>
#include <cstdint>

#define H 480
#define W 640
#define P 256

// swizzled, guard-padded row layout (shared by g_box and the smem band)
#define SWQ 176                   // 16B quads per row
#define SWF (SWQ * 4)             // 704 floats per row
#define GQ  4                     // left guard quads (16 floats)

// descriptor tiling: TY=15 -> 1024 blocks -> 7 waves x 15 rows (vs 7x16)
#define TY 15                     // output rows per block
#define CH 5                      // vertical chain depth per slab
#define BAND (TY + 32)            // 47 band rows
#define NTHREADS 240              // 3 slabs x 80 col-threads
#define GPAIRS 8                  // pairs per block
#define SMEM_DATA_BYTES (BAND * SWF * 4)        // 132,352
#define SMEM_BYTES (SMEM_DATA_BYTES + 16)       // + mbarrier

// Pre-swizzled box-average image with replicate guards (allocation-free)
__device__ __align__(16) float g_box[H * SWF];

// 16B-quad XOR swizzle (verified conflict-free for stride-2-quad phases)
__device__ __host__ __forceinline__ int swzq(int q) { return q ^ ((q >> 3) & 1); }

// ---------------------------------------------------------------------------
// Packed f32x2 helpers
// ---------------------------------------------------------------------------
__device__ __forceinline__ uint64_t pk2(float lo, float hi) {
    uint64_t r; asm("mov.b64 %0, {%1, %2};" : "=l"(r) : "f"(lo), "f"(hi)); return r;
}
__device__ __forceinline__ uint64_t mul2(uint64_t a, uint64_t b) {
    uint64_t r; asm("mul.rn.f32x2 %0, %1, %2;" : "=l"(r) : "l"(a), "l"(b)); return r;
}
__device__ __forceinline__ uint64_t fma2(uint64_t a, uint64_t b, uint64_t c) {
    uint64_t r; asm("fma.rn.f32x2 %0, %1, %2, %3;" : "=l"(r) : "l"(a), "l"(b), "l"(c)); return r;
}
__device__ __forceinline__ uint64_t add2(uint64_t a, uint64_t b) {
    uint64_t r; asm("add.rn.f32x2 %0, %1, %2;" : "=l"(r) : "l"(a), "l"(b)); return r;
}
__device__ __forceinline__ float2 upk2(uint64_t a) {
    float2 f; asm("mov.b64 {%0, %1}, %2;" : "=f"(f.x), "=f"(f.y) : "l"(a)); return f;
}

// ---------------------------------------------------------------------------
// Fused 5x5 box average -> pre-swizzled guard-padded g_box.
// ---------------------------------------------------------------------------
__global__ void box_kernel(const float* __restrict__ x) {
    int idx = blockIdx.x * blockDim.x + threadIdx.x;
    if (idx >= H * 168) return;
    int y = idx / 168;
    int t = idx - y * 168;
    float* orow = g_box + y * SWF;

    if (t < 160) {
        float4 s = make_float4(0.f, 0.f, 0.f, 0.f);
        if (t >= 1 && t <= 158) {
#pragma unroll
            for (int d = -2; d <= 2; d++) {
                int yc = min(max(y + d, 0), H - 1);
                const float* row = x + yc * W;
                float4 m1 = __ldg((const float4*)(row + 4 * t - 4));
                float4 c0 = __ldg((const float4*)(row + 4 * t));
                float4 p1 = __ldg((const float4*)(row + 4 * t + 4));
                float ss = c0.x + c0.y + c0.z;
                s.x += ss + m1.z + m1.w;
                s.y += ss + m1.w + c0.w;
                s.z += ss + c0.w + p1.x;
                s.w += c0.y + c0.z + c0.w + p1.x + p1.y;
            }
        } else {
            float r[4] = {0.f, 0.f, 0.f, 0.f};
#pragma unroll
            for (int d = -2; d <= 2; d++) {
                int yc = min(max(y + d, 0), H - 1);
                const float* row = x + yc * W;
#pragma unroll
                for (int k = 0; k < 4; k++) {
                    int xx = 4 * t + k;
#pragma unroll
                    for (int e = -2; e <= 2; e++) {
                        int xc = min(max(xx + e, 0), W - 1);
                        r[k] += row[xc];
                    }
                }
            }
            s = make_float4(r[0], r[1], r[2], r[3]);
        }
        const float inv = 1.0f / 25.0f;
        s.x *= inv; s.y *= inv; s.z *= inv; s.w *= inv;
        *(float4*)(orow + swzq(GQ + t) * 4) = s;
    } else {
        bool left = (t < 164);
        float v = 0.f;
#pragma unroll
        for (int d = -2; d <= 2; d++) {
            int yc = min(max(y + d, 0), H - 1);
            const float* row = x + yc * W;
            if (left) v += 3.f * row[0] + row[1] + row[2];
            else      v += 3.f * row[W - 1] + row[W - 2] + row[W - 3];
        }
        v *= (1.0f / 25.0f);
        int q = left ? (t - 160) : (GQ + 160 + (t - 164));
        *(float4*)(orow + swzq(q) * 4) = make_float4(v, v, v, v);
    }
}

// ---------------------------------------------------------------------------
// Horizontal lerp of one band row: 3 swizzled LDS.128 -> 4 packed pairs
// ---------------------------------------------------------------------------
template <int RR>
__device__ __forceinline__ void hrow8(const float* __restrict__ sp,
                                      int o0, int o1, int o2,
                                      uint64_t fx2, uint64_t omfx2, uint64_t* h) {
    float4 A = *(const float4*)(sp + o0);
    float4 B = *(const float4*)(sp + o1);
    float4 C = *(const float4*)(sp + o2);
    float w0, w1, w2, w3, w4, w5, w6, w7, w8;
    if      (RR == 0) { w0=A.x; w1=A.y; w2=A.z; w3=A.w; w4=B.x; w5=B.y; w6=B.z; w7=B.w; w8=C.x; }
    else if (RR == 1) { w0=A.y; w1=A.z; w2=A.w; w3=B.x; w4=B.y; w5=B.z; w6=B.w; w7=C.x; w8=C.y; }
    else if (RR == 2) { w0=A.z; w1=A.w; w2=B.x; w3=B.y; w4=B.z; w5=B.w; w6=C.x; w7=C.y; w8=C.z; }
    else              { w0=A.w; w1=B.x; w2=B.y; w3=B.z; w4=B.w; w5=C.x; w6=C.y; w7=C.z; w8=C.w; }
    h[0] = fma2(pk2(w1, w2), fx2, mul2(pk2(w0, w1), omfx2));
    h[1] = fma2(pk2(w3, w4), fx2, mul2(pk2(w2, w3), omfx2));
    h[2] = fma2(pk2(w5, w6), fx2, mul2(pk2(w4, w5), omfx2));
    h[3] = fma2(pk2(w7, w8), fx2, mul2(pk2(w6, w7), omfx2));
}

// ---------------------------------------------------------------------------
// CH-row chained sample, 8 cols wide. SUB folds subtraction via negated fy.
// acc: 4*CH packed pairs (CH rows x 4 pairs).
// ---------------------------------------------------------------------------
template <int RR, bool SUB>
__device__ __forceinline__ void rowsCx8(const float* __restrict__ sp,
                                        int o0, int o1, int o2,
                                        float fx, float fy, uint64_t* acc) {
    uint64_t fx2   = pk2(fx, fx);
    uint64_t omfx2 = pk2(1.0f - fx, 1.0f - fx);
    const float sgn = SUB ? -1.0f : 1.0f;
    uint64_t fy2   = pk2(sgn * fy, sgn * fy);
    uint64_t omfy2 = pk2(sgn * (1.0f - fy), sgn * (1.0f - fy));

    uint64_t hp[4], hc[4];
    hrow8<RR>(sp, o0, o1, o2, fx2, omfx2, hp);
#pragma unroll
    for (int i = 0; i < CH; i++) {
        sp += SWF;
        hrow8<RR>(sp, o0, o1, o2, fx2, omfx2, hc);
#pragma unroll
        for (int k = 0; k < 4; k++) {
            uint64_t o = fma2(hc[k], fy2, mul2(hp[k], omfy2));
            if (SUB) acc[4 * i + k] = add2(acc[4 * i + k], o);
            else     acc[4 * i + k] = o;
            hp[k] = hc[k];
        }
    }
}

template <bool SUB>
__device__ __forceinline__ void band_sample(const float* __restrict__ sb,
                                            int y0, int ybase, int gx,
                                            float dy, float dx, uint64_t* acc) {
    float py0 = (float)ybase + dy;
    float yAf = floorf(py0);
    float fy  = py0 - yAf;
    int slot0 = (int)yAf - (y0 - 16);     // in [0, BAND-CH-1]

    float ixf = floorf(dx);
    float fx  = dx - ixf;
    int c  = gx + (int)ixf;               // in [-16, 647]
    int qb = (c >> 2) + GQ;               // quad index incl guard
    int rr = c & 3;                       // warp-uniform (pair-level)
    int o0 = swzq(qb) * 4, o1 = swzq(qb + 1) * 4, o2 = swzq(qb + 2) * 4;

    const float* sp = sb + slot0 * SWF;
    switch (rr) {                         // uniform branch
        case 0:  rowsCx8<0, SUB>(sp, o0, o1, o2, fx, fy, acc); break;
        case 1:  rowsCx8<1, SUB>(sp, o0, o1, o2, fx, fy, acc); break;
        case 2:  rowsCx8<2, SUB>(sp, o0, o1, o2, fx, fy, acc); break;
        default: rowsCx8<3, SUB>(sp, o0, o1, o2, fx, fy, acc); break;
    }
}

// ---------------------------------------------------------------------------
// Descriptor kernel: TMA-bulk stages a 47-row pre-swizzled band, then
// 3 slabs x 80 cols compute 8 pairs (chain-5 per slab).
// ---------------------------------------------------------------------------
__global__ void __launch_bounds__(NTHREADS) descriptor_kernel(
    const float* __restrict__ offs, float* __restrict__ out)
{
    extern __shared__ float sb[];
    const int y0  = blockIdx.x * TY;
    const int tid = threadIdx.x;
    uint32_t sbu  = (uint32_t)__cvta_generic_to_shared(sb);
    uint32_t mbar = sbu + SMEM_DATA_BYTES;

    if (tid == 0) {
        asm volatile("mbarrier.init.shared.b64 [%0], 1;" :: "r"(mbar) : "memory");
        asm volatile("mbarrier.arrive.expect_tx.shared.b64 _, [%0], %1;"
                     :: "r"(mbar), "r"((uint32_t)(BAND * SWF * 4)) : "memory");
    }
    __syncthreads();
    if (tid < BAND) {
        int gy = min(max(y0 - 16 + tid, 0), H - 1);
        uint32_t dst = sbu + tid * (SWF * 4);
        const float* src = g_box + gy * SWF;
        asm volatile(
            "cp.async.bulk.shared::cluster.global.mbarrier::complete_tx::bytes "
            "[%0], [%1], %2, [%3];"
            :: "r"(dst), "l"(src), "r"((uint32_t)(SWF * 4)), "r"(mbar) : "memory");
    }
    {
        uint32_t done;
        asm volatile(
            "{\n\t.reg .pred p;\n\t"
            "mbarrier.try_wait.parity.acquire.cta.shared::cta.b64 p, [%1], %2;\n\t"
            "selp.b32 %0, 1, 0, p;\n\t}"
            : "=r"(done) : "r"(mbar), "r"(0u) : "memory");
        if (!done) {
            asm volatile(
                "{\n\t.reg .pred P1;\n\t"
                "WL%=:\n\t"
                "mbarrier.try_wait.parity.acquire.cta.shared::cta.b64 P1, [%0], %1, 0x989680;\n\t"
                "@P1 bra.uni WD%=;\n\t"
                "bra.uni WL%=;\n\t"
                "WD%=:\n\t}"
                :: "r"(mbar), "r"(0u) : "memory");
        }
    }

    const int slab  = tid / 80;             // 0..2
    const int col   = tid - slab * 80;      // 0..79
    const int gx    = col * 8;
    const int ybase = y0 + slab * CH;

    const int pbase = blockIdx.y * GPAIRS;
#pragma unroll 1
    for (int g = 0; g < GPAIRS; g++) {
        int p = pbase + g;
        float4 od = __ldg((const float4*)(offs + 4 * p));  // dy1,dx1,dy2,dx2

        uint64_t acc[4 * CH];
        band_sample<false>(sb, y0, ybase, gx, od.x, od.y, acc);
        band_sample<true >(sb, y0, ybase, gx, od.z, od.w, acc);

        float* op = out + ((size_t)p * H + ybase) * W + gx;
#pragma unroll
        for (int i = 0; i < CH; i++) {
            float2 a = upk2(acc[4 * i + 0]);
            float2 b = upk2(acc[4 * i + 1]);
            float2 c = upk2(acc[4 * i + 2]);
            float2 d = upk2(acc[4 * i + 3]);
            __stcs((float4*)(op + (size_t)i * W),     make_float4(a.x, a.y, b.x, b.y));
            __stcs((float4*)(op + (size_t)i * W + 4), make_float4(c.x, c.y, d.x, d.y));
        }
    }
}

extern "C" void kernel_launch(void* const* d_in, const int* in_sizes, int n_in,
                              void* d_out, int out_size) {
    const float* x    = (const float*)d_in[0];   // [1,1,480,640]
    const float* offs = (const float*)d_in[1];   // [256,2,2]
    float* out = (float*)d_out;                  // [1,256,480,640]

    cudaFuncSetAttribute(descriptor_kernel,
                         cudaFuncAttributeMaxDynamicSharedMemorySize, SMEM_BYTES);

    const int nbox = H * 168;                    // 80640
    box_kernel<<<(nbox + 255) / 256, 256>>>(x);

    dim3 grid(H / TY, P / GPAIRS, 1);            // (32, 32) = 1024 blocks
    descriptor_kernel<<<grid, NTHREADS, SMEM_BYTES>>>(offs, out);
}